// round 12
// baseline (speedup 1.0000x reference)
#include <cuda_runtime.h>
#include <cuda_fp16.h>
#include <mma.h>
#include <math.h>
#include <cstdint>

using namespace nvcuda;

#define BB 4
#define TT 1024
#define DD 1024
#define HH 16
#define HDIM 64
#define BT (BB*TT)

// fp32 scratch
__device__ float g_s[(size_t)BB * HH * TT * TT];   // scores fp32 [b,h,kt,qt] (lower tri)

// fp16 buffers
__device__ __half g_xhi[(size_t)BT * DD];
__device__ __half g_xlo[(size_t)BT * DD];
__device__ __half g_whi[(size_t)4 * DD * DD];      // Wk,Wq,Wv,Wp (hi / rounded)
__device__ __half g_wplo[(size_t)DD * DD];         // Wp lo (proj is 3-term)
__device__ __half g_khi[(size_t)BT * DD];
__device__ __half g_klo[(size_t)BT * DD];
__device__ __half g_qhi[(size_t)BT * DD];
__device__ __half g_vhi[(size_t)BT * DD];
__device__ __half g_ahi[(size_t)BT * DD];
__device__ __half g_alo[(size_t)BT * DD];
__device__ __half g_swhi[(size_t)BB * HH * TT * TT];

#define NEG_INF __int_as_float(0xff800000)

__device__ __forceinline__ void cpa16(void* sdst, const void* gsrc) {
    uint32_t s = (uint32_t)__cvta_generic_to_shared(sdst);
    asm volatile("cp.async.cg.shared.global [%0], [%1], 16;" :: "r"(s), "l"(gsrc));
}
__device__ __forceinline__ void cpa_commit() {
    asm volatile("cp.async.commit_group;");
}
template <int N> __device__ __forceinline__ void cpa_wait() {
    asm volatile("cp.async.wait_group %0;" :: "n"(N));
}

// ---------------------------------------------------------------------------
// One fused conversion kernel: y=0: x -> fp16 hi/lo; y=1..3: W -> fp16 (round);
// y=4: Wp -> fp16 hi/lo.
// ---------------------------------------------------------------------------
__global__ void cvt_all(const float* __restrict__ x,
                        const float* __restrict__ Wk, const float* __restrict__ Wq,
                        const float* __restrict__ Wv, const float* __restrict__ Wp,
                        __half* __restrict__ xhi, __half* __restrict__ xlo,
                        __half* __restrict__ whi, __half* __restrict__ wplo) {
    const int t = blockIdx.x * 256 + threadIdx.x;
    const int y = blockIdx.y;
    const size_t WSZ = (size_t)DD * DD;
    if (y == 0) {
        if (t >= BT * DD / 4) return;
        float4 v = ((const float4*)x)[t];
        __half h0 = __float2half_rn(v.x), h1 = __float2half_rn(v.y);
        __half h2 = __float2half_rn(v.z), h3 = __float2half_rn(v.w);
        ((__half2*)xhi)[2*t]   = __halves2half2(h0, h1);
        ((__half2*)xhi)[2*t+1] = __halves2half2(h2, h3);
        ((__half2*)xlo)[2*t]   = __halves2half2(__float2half_rn(v.x - __half2float(h0)),
                                                __float2half_rn(v.y - __half2float(h1)));
        ((__half2*)xlo)[2*t+1] = __halves2half2(__float2half_rn(v.z - __half2float(h2)),
                                                __float2half_rn(v.w - __half2float(h3)));
    } else {
        if (t >= DD * DD / 4) return;
        const float* src = (y == 1) ? Wk : (y == 2) ? Wq : (y == 3) ? Wv : Wp;
        float4 v = ((const float4*)src)[t];
        __half h0 = __float2half_rn(v.x), h1 = __float2half_rn(v.y);
        __half h2 = __float2half_rn(v.z), h3 = __float2half_rn(v.w);
        __half2* dst = (__half2*)(whi + (size_t)(y - 1) * WSZ);
        dst[2*t]   = __halves2half2(h0, h1);
        dst[2*t+1] = __halves2half2(h2, h3);
        if (y == 4) {
            ((__half2*)wplo)[2*t]   = __halves2half2(__float2half_rn(v.x - __half2float(h0)),
                                                     __float2half_rn(v.y - __half2float(h1)));
            ((__half2*)wplo)[2*t+1] = __halves2half2(__float2half_rn(v.z - __half2float(h2)),
                                                     __float2half_rn(v.w - __half2float(h3)));
        }
    }
}

// ---------------------------------------------------------------------------
// QKV fused GEMM: z = blockIdx.z picks (W, bias, output). 2-term A-split.
// z=0 (K) also writes lo residual. 128x128 tile, BK=32, 3-stage pipeline.
// ---------------------------------------------------------------------------
#define LDT 48

__global__ __launch_bounds__(256, 1)
void gemm_qkv(const __half* __restrict__ Ahi,
              const __half* __restrict__ Alo,
              const __half* __restrict__ Wall,
              const float* __restrict__ bk, const float* __restrict__ bq,
              const float* __restrict__ bv,
              __half* __restrict__ Khi, __half* __restrict__ Klo,
              __half* __restrict__ Qhi, __half* __restrict__ Vhi) {
    extern __shared__ __half smem[];   // 3 stages * 3 * 128 * LDT
    constexpr int TILE = 128 * LDT;
    constexpr int STGE = 3 * TILE;
    const int K = DD, N = DD;

    const int z = blockIdx.z;
    const __half* Bhi = Wall + (size_t)z * DD * DD;
    const float* bias = (z == 0) ? bk : (z == 1) ? bq : bv;
    __half* Chi = (z == 0) ? Khi : (z == 1) ? Qhi : Vhi;

    const int tid = threadIdx.x, wid = tid >> 5;
    const int warp_m = wid & 3, warp_n = wid >> 2;
    const int m0 = blockIdx.y * 128, n0 = blockIdx.x * 128;

    wmma::fragment<wmma::accumulator, 16, 16, 16, float> acc[2][4];
    #pragma unroll
    for (int i = 0; i < 2; i++)
        #pragma unroll
        for (int j = 0; j < 4; j++) wmma::fill_fragment(acc[i][j], 0.0f);

    auto load_stage = [&](int st, int k0) {
        __half* base = smem + st * STGE;
        #pragma unroll
        for (int u = tid; u < 512; u += 256) {
            int r = u >> 2, cq = u & 3;
            size_t offA = (size_t)(m0 + r) * K + k0 + cq * 8;
            size_t offB = (size_t)(n0 + r) * K + k0 + cq * 8;
            cpa16(&base[r * LDT + cq * 8], Ahi + offA);
            cpa16(&base[TILE + r * LDT + cq * 8], Alo + offA);
            cpa16(&base[2 * TILE + r * LDT + cq * 8], Bhi + offB);
        }
        cpa_commit();
    };

    const int nIter = K / 32;
    load_stage(0, 0);
    load_stage(1, 32);

    int st = 0;
    for (int i = 0; i < nIter; i++) {
        if (i + 2 < nIter) cpa_wait<1>(); else cpa_wait<0>();
        __syncthreads();
        if (i + 2 < nIter) {
            int nst = st + 2; if (nst >= 3) nst -= 3;
            load_stage(nst, (i + 2) * 32);
        }

        __half* base = smem + st * STGE;
        __half* sAhi = base;
        __half* sAlo = base + TILE;
        __half* sBhi = base + 2 * TILE;

        #pragma unroll
        for (int kk = 0; kk < 32; kk += 16) {
            wmma::fragment<wmma::matrix_a, 16, 16, 16, __half, wmma::row_major> aHi[2], aLo[2];
            wmma::fragment<wmma::matrix_b, 16, 16, 16, __half, wmma::col_major> bHi[4];
            #pragma unroll
            for (int ii = 0; ii < 2; ii++) {
                wmma::load_matrix_sync(aHi[ii], &sAhi[(warp_m * 32 + ii * 16) * LDT + kk], LDT);
                wmma::load_matrix_sync(aLo[ii], &sAlo[(warp_m * 32 + ii * 16) * LDT + kk], LDT);
            }
            #pragma unroll
            for (int j = 0; j < 4; j++)
                wmma::load_matrix_sync(bHi[j], &sBhi[(warp_n * 64 + j * 16) * LDT + kk], LDT);
            #pragma unroll
            for (int ii = 0; ii < 2; ii++)
                #pragma unroll
                for (int j = 0; j < 4; j++) {
                    wmma::mma_sync(acc[ii][j], aHi[ii], bHi[j], acc[ii][j]);
                    wmma::mma_sync(acc[ii][j], aLo[ii], bHi[j], acc[ii][j]);
                }
        }
        if (++st == 3) st = 0;
    }
    __syncthreads();

    float* sC = (float*)smem;   // 128 x 132
    #pragma unroll
    for (int ii = 0; ii < 2; ii++)
        #pragma unroll
        for (int j = 0; j < 4; j++)
            wmma::store_matrix_sync(&sC[(warp_m * 32 + ii * 16) * 132 + warp_n * 64 + j * 16],
                                    acc[ii][j], 132, wmma::mem_row_major);
    __syncthreads();

    #pragma unroll
    for (int it = 0; it < 16; it++) {
        int idx = tid + it * 256;            // 0..4095
        int r = idx >> 5, c4 = idx & 31;
        float4 v = *(float4*)&sC[r * 132 + c4 * 4];
        float4 bb = *(const float4*)&bias[n0 + c4 * 4];
        v.x += bb.x; v.y += bb.y; v.z += bb.z; v.w += bb.w;
        size_t off = (size_t)(m0 + r) * N + n0 + c4 * 4;
        __half h0 = __float2half_rn(v.x), h1 = __float2half_rn(v.y);
        __half h2 = __float2half_rn(v.z), h3 = __float2half_rn(v.w);
        ((__half2*)(Chi + off))[0] = __halves2half2(h0, h1);
        ((__half2*)(Chi + off))[1] = __halves2half2(h2, h3);
        if (z == 0) {
            ((__half2*)(Klo + off))[0] = __halves2half2(__float2half_rn(v.x - __half2float(h0)),
                                                        __float2half_rn(v.y - __half2float(h1)));
            ((__half2*)(Klo + off))[1] = __halves2half2(__float2half_rn(v.z - __half2float(h2)),
                                                        __float2half_rn(v.w - __half2float(h3)));
        }
    }
}

// ---------------------------------------------------------------------------
// Proj GEMM: 3-term (Ahi,Alo) x (Bhi,Blo), fp32 out + bias.
// ---------------------------------------------------------------------------
__global__ __launch_bounds__(256, 1)
void gemm_proj(const __half* __restrict__ Ahi,
               const __half* __restrict__ Alo,
               const __half* __restrict__ Bhi,
               const __half* __restrict__ Blo,
               const float* __restrict__ bias,
               float* __restrict__ Cf) {
    extern __shared__ __half smem[];   // 3 stages * 4 * 128 * LDT
    constexpr int TILE = 128 * LDT;
    constexpr int STGE = 4 * TILE;
    const int K = DD, N = DD;

    const int tid = threadIdx.x, wid = tid >> 5;
    const int warp_m = wid & 3, warp_n = wid >> 2;
    const int m0 = blockIdx.y * 128, n0 = blockIdx.x * 128;

    wmma::fragment<wmma::accumulator, 16, 16, 16, float> acc[2][4];
    #pragma unroll
    for (int i = 0; i < 2; i++)
        #pragma unroll
        for (int j = 0; j < 4; j++) wmma::fill_fragment(acc[i][j], 0.0f);

    auto load_stage = [&](int st, int k0) {
        __half* base = smem + st * STGE;
        #pragma unroll
        for (int u = tid; u < 512; u += 256) {
            int r = u >> 2, cq = u & 3;
            size_t offA = (size_t)(m0 + r) * K + k0 + cq * 8;
            size_t offB = (size_t)(n0 + r) * K + k0 + cq * 8;
            cpa16(&base[r * LDT + cq * 8], Ahi + offA);
            cpa16(&base[TILE + r * LDT + cq * 8], Alo + offA);
            cpa16(&base[2 * TILE + r * LDT + cq * 8], Bhi + offB);
            cpa16(&base[3 * TILE + r * LDT + cq * 8], Blo + offB);
        }
        cpa_commit();
    };

    const int nIter = K / 32;
    load_stage(0, 0);
    load_stage(1, 32);

    int st = 0;
    for (int i = 0; i < nIter; i++) {
        if (i + 2 < nIter) cpa_wait<1>(); else cpa_wait<0>();
        __syncthreads();
        if (i + 2 < nIter) {
            int nst = st + 2; if (nst >= 3) nst -= 3;
            load_stage(nst, (i + 2) * 32);
        }

        __half* base = smem + st * STGE;
        __half* sAhi = base;
        __half* sAlo = base + TILE;
        __half* sBhi = base + 2 * TILE;
        __half* sBlo = base + 3 * TILE;

        #pragma unroll
        for (int kk = 0; kk < 32; kk += 16) {
            wmma::fragment<wmma::matrix_a, 16, 16, 16, __half, wmma::row_major> aHi[2], aLo[2];
            wmma::fragment<wmma::matrix_b, 16, 16, 16, __half, wmma::col_major> bHi[4], bLo[4];
            #pragma unroll
            for (int ii = 0; ii < 2; ii++) {
                wmma::load_matrix_sync(aHi[ii], &sAhi[(warp_m * 32 + ii * 16) * LDT + kk], LDT);
                wmma::load_matrix_sync(aLo[ii], &sAlo[(warp_m * 32 + ii * 16) * LDT + kk], LDT);
            }
            #pragma unroll
            for (int j = 0; j < 4; j++) {
                wmma::load_matrix_sync(bHi[j], &sBhi[(warp_n * 64 + j * 16) * LDT + kk], LDT);
                wmma::load_matrix_sync(bLo[j], &sBlo[(warp_n * 64 + j * 16) * LDT + kk], LDT);
            }
            #pragma unroll
            for (int ii = 0; ii < 2; ii++)
                #pragma unroll
                for (int j = 0; j < 4; j++) {
                    wmma::mma_sync(acc[ii][j], aHi[ii], bHi[j], acc[ii][j]);
                    wmma::mma_sync(acc[ii][j], aLo[ii], bHi[j], acc[ii][j]);
                    wmma::mma_sync(acc[ii][j], aHi[ii], bLo[j], acc[ii][j]);
                }
        }
        if (++st == 3) st = 0;
    }
    __syncthreads();

    float* sC = (float*)smem;   // 128 x 132
    #pragma unroll
    for (int ii = 0; ii < 2; ii++)
        #pragma unroll
        for (int j = 0; j < 4; j++)
            wmma::store_matrix_sync(&sC[(warp_m * 32 + ii * 16) * 132 + warp_n * 64 + j * 16],
                                    acc[ii][j], 132, wmma::mem_row_major);
    __syncthreads();

    #pragma unroll
    for (int it = 0; it < 16; it++) {
        int idx = tid + it * 256;
        int r = idx >> 5, c4 = idx & 31;
        float4 v = *(float4*)&sC[r * 132 + c4 * 4];
        float4 bb = *(const float4*)&bias[n0 + c4 * 4];
        v.x += bb.x; v.y += bb.y; v.z += bb.z; v.w += bb.w;
        *(float4*)&Cf[(size_t)(m0 + r) * N + n0 + c4 * 4] = v;
    }
}

// ---------------------------------------------------------------------------
// Tensor-core scores (lower-tri blocks only): 2-term (Khi+Klo)·Qhi, /32.
// ---------------------------------------------------------------------------
#define LDS 72
__global__ __launch_bounds__(256)
void scores_tc(const __half* __restrict__ Khi, const __half* __restrict__ Klo,
               const __half* __restrict__ Qhi, float* __restrict__ S) {
    if (blockIdx.x > blockIdx.y) return;
    __shared__ __half sKhi[64 * LDS], sKlo[64 * LDS], sQhi[64 * LDS];
    const int bh = blockIdx.z;
    const int b = bh >> 4, h = bh & 15;
    const int kt0 = blockIdx.y * 64, qt0 = blockIdx.x * 64;
    const int tid = threadIdx.x, wid = tid >> 5;
    const int warp_m = wid >> 1, warp_n = wid & 1;

    const size_t baseK = (size_t)(b * TT + kt0) * DD + h * HDIM;
    const size_t baseQ = (size_t)(b * TT + qt0) * DD + h * HDIM;
    #pragma unroll
    for (int u = tid; u < 512; u += 256) {
        int r = u >> 3, cq = u & 7;
        *(uint4*)(&sKhi[r * LDS + cq * 8]) = ((const uint4*)(Khi + baseK + (size_t)r * DD))[cq];
        *(uint4*)(&sKlo[r * LDS + cq * 8]) = ((const uint4*)(Klo + baseK + (size_t)r * DD))[cq];
        *(uint4*)(&sQhi[r * LDS + cq * 8]) = ((const uint4*)(Qhi + baseQ + (size_t)r * DD))[cq];
    }
    __syncthreads();

    wmma::fragment<wmma::accumulator, 16, 16, 16, float> acc[2];
    wmma::fill_fragment(acc[0], 0.0f);
    wmma::fill_fragment(acc[1], 0.0f);

    #pragma unroll
    for (int kk = 0; kk < 64; kk += 16) {
        wmma::fragment<wmma::matrix_a, 16, 16, 16, __half, wmma::row_major> aHi, aLo;
        wmma::fragment<wmma::matrix_b, 16, 16, 16, __half, wmma::col_major> bHi[2];
        wmma::load_matrix_sync(aHi, &sKhi[(warp_m * 16) * LDS + kk], LDS);
        wmma::load_matrix_sync(aLo, &sKlo[(warp_m * 16) * LDS + kk], LDS);
        #pragma unroll
        for (int j = 0; j < 2; j++)
            wmma::load_matrix_sync(bHi[j], &sQhi[(warp_n * 32 + j * 16) * LDS + kk], LDS);
        #pragma unroll
        for (int j = 0; j < 2; j++) {
            wmma::mma_sync(acc[j], aHi, bHi[j], acc[j]);
            wmma::mma_sync(acc[j], aLo, bHi[j], acc[j]);
        }
    }
    #pragma unroll
    for (int j = 0; j < 2; j++) {
        #pragma unroll
        for (int e = 0; e < acc[j].num_elements; e++) acc[j].x[e] *= 0.03125f;
        float* sp = S + (size_t)bh * TT * TT + (size_t)(kt0 + warp_m * 16) * TT
                      + qt0 + warp_n * 32 + j * 16;
        wmma::store_matrix_sync(sp, acc[j], TT, wmma::mem_row_major);
    }
}

// ---------------------------------------------------------------------------
// Fused masked softmax + transposed wout + fp16 weights (hi only).
// 512 threads = 16 warps, one warp per head.
// ---------------------------------------------------------------------------
#define SMLD 1033
__global__ __launch_bounds__(512)
void fused_sm(const float* __restrict__ S, float* __restrict__ wout,
              __half* __restrict__ whi) {
    extern __shared__ float tile[];   // 16 * SMLD
    const int bkt = blockIdx.x;
    const int b = bkt >> 10, kt = bkt & 1023;
    const int h = threadIdx.x >> 5, lane = threadIdx.x & 31;

    const size_t rowoff = ((size_t)(b * HH + h) * TT + kt) * TT;
    const float* row = S + rowoff;
    __half* hrow = whi + rowoff;

    float v[32];
    float m = NEG_INF;
    #pragma unroll
    for (int i = 0; i < 32; i++) {
        int q = lane + i * 32;
        if (q <= kt) { v[i] = row[q]; m = fmaxf(m, v[i]); }
        else v[i] = NEG_INF;
    }
    #pragma unroll
    for (int o = 16; o > 0; o >>= 1) m = fmaxf(m, __shfl_xor_sync(0xffffffffu, m, o));
    float s = 0.f;
    #pragma unroll
    for (int i = 0; i < 32; i++) {
        int q = lane + i * 32;
        if (q <= kt) { v[i] = __expf(v[i] - m); s += v[i]; }
    }
    #pragma unroll
    for (int o = 16; o > 0; o >>= 1) s += __shfl_xor_sync(0xffffffffu, s, o);
    const float inv = 1.0f / s;

    #pragma unroll
    for (int i = 0; i < 32; i++) {
        int q = lane + i * 32;
        if (q <= kt) {
            float w = v[i] * inv;
            tile[h * SMLD + q] = w;
            hrow[q] = __float2half_rn(w);
        } else {
            tile[h * SMLD + q] = 0.0f;
        }
    }
    const int qpad = ((kt >> 6) + 1) << 6;
    for (int q = kt + 1 + lane; q < qpad; q += 32)
        hrow[q] = __float2half_rn(0.f);
    __syncthreads();

    float* wo = wout + (size_t)bkt * TT * HH;
    #pragma unroll
    for (int it = 0; it < 32; it++) {
        int idx = threadIdx.x + it * 512;    // 0..16383
        int q = idx >> 4, hl = idx & 15;
        wo[idx] = tile[hl * SMLD + q];
    }
}

// ---------------------------------------------------------------------------
// Tensor-core AV: 1-term Whi·Vhi, split epilogue -> ahi/alo
// ---------------------------------------------------------------------------
__global__ __launch_bounds__(256)
void av_tc(const __half* __restrict__ Whi, const __half* __restrict__ Vhi,
           __half* __restrict__ Ahi, __half* __restrict__ Alo) {
    __shared__ __align__(16) char smraw[2 * 64 * LDS * 2 + 64 * 68 * 4];
    __half* sWhi = (__half*)smraw;
    __half* sVhi = sWhi + 64 * LDS;

    const int bh = blockIdx.y;
    const int b = bh >> 4, h = bh & 15;
    const int m0 = blockIdx.x * 64;
    const int tid = threadIdx.x, wid = tid >> 5;
    const int warp_m = wid >> 1, warp_n = wid & 1;

    const __half* Wh = Whi + (size_t)bh * TT * TT;
    const size_t vbase = (size_t)b * TT * DD + h * HDIM;

    wmma::fragment<wmma::accumulator, 16, 16, 16, float> acc[2];
    wmma::fill_fragment(acc[0], 0.0f);
    wmma::fill_fragment(acc[1], 0.0f);

    const int kend = m0 + 64;
    for (int q0 = 0; q0 < kend; q0 += 64) {
        #pragma unroll
        for (int u = tid; u < 512; u += 256) {
            int r = u >> 3, cq = u & 7;
            size_t offW = (size_t)(m0 + r) * TT + q0;
            *(uint4*)(&sWhi[r * LDS + cq * 8]) = ((const uint4*)(Wh + offW))[cq];
            *(uint4*)(&sVhi[r * LDS + cq * 8]) = ((const uint4*)(Vhi + vbase + (size_t)(q0 + r) * DD))[cq];
        }
        __syncthreads();
        #pragma unroll
        for (int kk = 0; kk < 64; kk += 16) {
            wmma::fragment<wmma::matrix_a, 16, 16, 16, __half, wmma::row_major> aHi;
            wmma::fragment<wmma::matrix_b, 16, 16, 16, __half, wmma::row_major> bHi[2];
            wmma::load_matrix_sync(aHi, &sWhi[(warp_m * 16) * LDS + kk], LDS);
            #pragma unroll
            for (int j = 0; j < 2; j++)
                wmma::load_matrix_sync(bHi[j], &sVhi[kk * LDS + warp_n * 32 + j * 16], LDS);
            #pragma unroll
            for (int j = 0; j < 2; j++)
                wmma::mma_sync(acc[j], aHi, bHi[j], acc[j]);
        }
        __syncthreads();
    }

    float* sC = (float*)(smraw + 2 * 64 * LDS * 2);   // 64 x 68
    #pragma unroll
    for (int j = 0; j < 2; j++)
        wmma::store_matrix_sync(&sC[(warp_m * 16) * 68 + warp_n * 32 + j * 16],
                                acc[j], 68, wmma::mem_row_major);
    __syncthreads();

    #pragma unroll
    for (int it = 0; it < 4; it++) {
        int idx = tid + it * 256;            // 0..1023
        int r = idx >> 4, c4 = idx & 15;
        float4 v = *(float4*)&sC[r * 68 + c4 * 4];
        size_t off = (size_t)(b * TT + m0 + r) * DD + h * HDIM + c4 * 4;
        __half h0 = __float2half_rn(v.x), h1 = __float2half_rn(v.y);
        __half h2 = __float2half_rn(v.z), h3 = __float2half_rn(v.w);
        ((__half2*)(Ahi + off))[0] = __halves2half2(h0, h1);
        ((__half2*)(Ahi + off))[1] = __halves2half2(h2, h3);
        ((__half2*)(Alo + off))[0] = __halves2half2(__float2half_rn(v.x - __half2float(h0)),
                                                    __float2half_rn(v.y - __half2float(h1)));
        ((__half2*)(Alo + off))[1] = __halves2half2(__float2half_rn(v.z - __half2float(h2)),
                                                    __float2half_rn(v.w - __half2float(h3)));
    }
}

// ---------------------------------------------------------------------------
extern "C" void kernel_launch(void* const* d_in, const int* in_sizes, int n_in,
                              void* d_out, int out_size) {
    const float* x  = (const float*)d_in[0];
    const float* Wk = (const float*)d_in[4];
    const float* bk = (const float*)d_in[5];
    const float* Wq = (const float*)d_in[6];
    const float* bq = (const float*)d_in[7];
    const float* Wv = (const float*)d_in[8];
    const float* bv = (const float*)d_in[9];
    const float* Wp = (const float*)d_in[10];
    const float* bp = (const float*)d_in[11];

    float* out  = (float*)d_out;
    float* wout = out + (size_t)BT * DD;

    float* gs;
    __half *xhi, *xlo, *whi, *wplo, *khi, *klo, *qhi, *vhi, *ahi, *alo, *swhi;
    cudaGetSymbolAddress((void**)&gs, g_s);
    cudaGetSymbolAddress((void**)&xhi, g_xhi);
    cudaGetSymbolAddress((void**)&xlo, g_xlo);
    cudaGetSymbolAddress((void**)&whi, g_whi);
    cudaGetSymbolAddress((void**)&wplo, g_wplo);
    cudaGetSymbolAddress((void**)&khi, g_khi);
    cudaGetSymbolAddress((void**)&klo, g_klo);
    cudaGetSymbolAddress((void**)&qhi, g_qhi);
    cudaGetSymbolAddress((void**)&vhi, g_vhi);
    cudaGetSymbolAddress((void**)&ahi, g_ahi);
    cudaGetSymbolAddress((void**)&alo, g_alo);
    cudaGetSymbolAddress((void**)&swhi, g_swhi);

    const size_t WSZ = (size_t)DD * DD;

    const size_t gsm3 = (size_t)3 * 3 * 128 * LDT * sizeof(__half);   // 110592
    const size_t gsm4 = (size_t)3 * 4 * 128 * LDT * sizeof(__half);   // 147456
    cudaFuncSetAttribute(gemm_qkv,  cudaFuncAttributeMaxDynamicSharedMemorySize, (int)gsm3);
    cudaFuncSetAttribute(gemm_proj, cudaFuncAttributeMaxDynamicSharedMemorySize, (int)gsm4);
    const size_t smsz = (size_t)HH * SMLD * sizeof(float);            // 66112
    cudaFuncSetAttribute(fused_sm, cudaFuncAttributeMaxDynamicSharedMemorySize, (int)smsz);

    cvt_all<<<dim3(4096, 5), 256>>>(x, Wk, Wq, Wv, Wp, xhi, xlo, whi, wplo);

    dim3 qkv_grid(DD / 128, BT / 128, 3);
    gemm_qkv<<<qkv_grid, 256, gsm3>>>(xhi, xlo, whi, bk, bq, bv, khi, klo, qhi, vhi);

    dim3 sc_grid(TT / 64, TT / 64, BB * HH);
    scores_tc<<<sc_grid, 256>>>(khi, klo, qhi, gs);

    fused_sm<<<BB * TT, 512, smsz>>>(gs, wout, swhi);

    dim3 av_grid(TT / 64, BB * HH);
    av_tc<<<av_grid, 256>>>(swhi, vhi, ahi, alo);

    dim3 pgrid(DD / 128, BT / 128);
    gemm_proj<<<pgrid, 256, gsm4>>>(ahi, alo, whi + 3 * WSZ, wplo, bp, out);
}

// round 16
// speedup vs baseline: 1.5215x; 1.5215x over previous
#include <cuda_runtime.h>
#include <cuda_fp16.h>
#include <mma.h>
#include <math.h>
#include <cstdint>

using namespace nvcuda;

#define BB 4
#define TT 1024
#define DD 1024
#define HH 16
#define HDIM 64
#define BT (BB*TT)

// fp32 scratch
__device__ float g_s[(size_t)BB * HH * TT * TT];   // scores fp32 [b,h,kt,qt] (lower tri)

// fp16 buffers
__device__ __half g_xhi[(size_t)BT * DD];
__device__ __half g_xlo[(size_t)BT * DD];
__device__ __half g_whi[(size_t)4 * DD * DD];      // Wk,Wq,Wv,Wp (hi / rounded)
__device__ __half g_wplo[(size_t)DD * DD];         // Wp lo (proj is 3-term)
__device__ __half g_khi[(size_t)BT * DD];
__device__ __half g_klo[(size_t)BT * DD];
__device__ __half g_qhi[(size_t)BT * DD];
__device__ __half g_vhi[(size_t)BT * DD];
__device__ __half g_ahi[(size_t)BT * DD];
__device__ __half g_alo[(size_t)BT * DD];
__device__ __half g_swhi[(size_t)BB * HH * TT * TT];

#define NEG_INF __int_as_float(0xff800000)

__device__ __forceinline__ void cpa16(void* sdst, const void* gsrc) {
    uint32_t s = (uint32_t)__cvta_generic_to_shared(sdst);
    asm volatile("cp.async.cg.shared.global [%0], [%1], 16;" :: "r"(s), "l"(gsrc));
}
__device__ __forceinline__ void cpa_commit() {
    asm volatile("cp.async.commit_group;");
}
template <int N> __device__ __forceinline__ void cpa_wait() {
    asm volatile("cp.async.wait_group %0;" :: "n"(N));
}

// ---------------------------------------------------------------------------
// One fused conversion kernel: y=0: x -> fp16 hi/lo; y=1..3: W -> fp16 (round);
// y=4: Wp -> fp16 hi/lo.
// ---------------------------------------------------------------------------
__global__ void cvt_all(const float* __restrict__ x,
                        const float* __restrict__ Wk, const float* __restrict__ Wq,
                        const float* __restrict__ Wv, const float* __restrict__ Wp,
                        __half* __restrict__ xhi, __half* __restrict__ xlo,
                        __half* __restrict__ whi, __half* __restrict__ wplo) {
    const int t = blockIdx.x * 256 + threadIdx.x;
    const int y = blockIdx.y;
    const size_t WSZ = (size_t)DD * DD;
    if (y == 0) {
        if (t >= BT * DD / 4) return;
        float4 v = ((const float4*)x)[t];
        __half h0 = __float2half_rn(v.x), h1 = __float2half_rn(v.y);
        __half h2 = __float2half_rn(v.z), h3 = __float2half_rn(v.w);
        ((__half2*)xhi)[2*t]   = __halves2half2(h0, h1);
        ((__half2*)xhi)[2*t+1] = __halves2half2(h2, h3);
        ((__half2*)xlo)[2*t]   = __halves2half2(__float2half_rn(v.x - __half2float(h0)),
                                                __float2half_rn(v.y - __half2float(h1)));
        ((__half2*)xlo)[2*t+1] = __halves2half2(__float2half_rn(v.z - __half2float(h2)),
                                                __float2half_rn(v.w - __half2float(h3)));
    } else {
        if (t >= DD * DD / 4) return;
        const float* src = (y == 1) ? Wk : (y == 2) ? Wq : (y == 3) ? Wv : Wp;
        float4 v = ((const float4*)src)[t];
        __half h0 = __float2half_rn(v.x), h1 = __float2half_rn(v.y);
        __half h2 = __float2half_rn(v.z), h3 = __float2half_rn(v.w);
        __half2* dst = (__half2*)(whi + (size_t)(y - 1) * WSZ);
        dst[2*t]   = __halves2half2(h0, h1);
        dst[2*t+1] = __halves2half2(h2, h3);
        if (y == 4) {
            ((__half2*)wplo)[2*t]   = __halves2half2(__float2half_rn(v.x - __half2float(h0)),
                                                     __float2half_rn(v.y - __half2float(h1)));
            ((__half2*)wplo)[2*t+1] = __halves2half2(__float2half_rn(v.z - __half2float(h2)),
                                                     __float2half_rn(v.w - __half2float(h3)));
        }
    }
}

// ---------------------------------------------------------------------------
// Pipelined fp16 GEMM: C = A @ W.T + bias.
// NT=3: 2-term (Ahi*Bhi + Alo*Bhi).  NT=4: 3-term (+ Ahi*Blo).
// EPI: 0 = fp32 C; 1 = fp16 hi only; 2 = fp16 hi+lo.
// 128x128 tile, BK=32, 3-stage cp.async pipeline. (round-10 proven config)
// ---------------------------------------------------------------------------
#define LDT 48

template <int NT, int EPI>
__global__ __launch_bounds__(256, 1)
void gemm_fp16(const __half* __restrict__ Ahi,
               const __half* __restrict__ Alo,
               const __half* __restrict__ Bhi,
               const __half* __restrict__ Blo,
               const float* __restrict__ bias,
               float* __restrict__ Cf,
               __half* __restrict__ Chi,
               __half* __restrict__ Clo,
               int M, int N, int K) {
    extern __shared__ __half smem[];   // 3 stages * NT * 128 * LDT
    constexpr int TILE = 128 * LDT;
    constexpr int STGE = NT * TILE;

    const int tid = threadIdx.x, wid = tid >> 5;
    const int warp_m = wid & 3, warp_n = wid >> 2;
    const int m0 = blockIdx.y * 128, n0 = blockIdx.x * 128;

    wmma::fragment<wmma::accumulator, 16, 16, 16, float> acc[2][4];
    #pragma unroll
    for (int i = 0; i < 2; i++)
        #pragma unroll
        for (int j = 0; j < 4; j++) wmma::fill_fragment(acc[i][j], 0.0f);

    auto load_stage = [&](int st, int k0) {
        __half* base = smem + st * STGE;
        #pragma unroll
        for (int u = tid; u < 512; u += 256) {
            int r = u >> 2, cq = u & 3;
            size_t offA = (size_t)(m0 + r) * K + k0 + cq * 8;
            size_t offB = (size_t)(n0 + r) * K + k0 + cq * 8;
            cpa16(&base[r * LDT + cq * 8], Ahi + offA);
            cpa16(&base[TILE + r * LDT + cq * 8], Alo + offA);
            cpa16(&base[2 * TILE + r * LDT + cq * 8], Bhi + offB);
            if (NT == 4) cpa16(&base[3 * TILE + r * LDT + cq * 8], Blo + offB);
        }
        cpa_commit();
    };

    const int nIter = K / 32;
    load_stage(0, 0);
    load_stage(1, 32);

    int st = 0;
    for (int i = 0; i < nIter; i++) {
        if (i + 2 < nIter) cpa_wait<1>(); else cpa_wait<0>();
        __syncthreads();
        if (i + 2 < nIter) {
            int nst = st + 2; if (nst >= 3) nst -= 3;
            load_stage(nst, (i + 2) * 32);
        }

        __half* base = smem + st * STGE;
        __half* sAhi = base;
        __half* sAlo = base + TILE;
        __half* sBhi = base + 2 * TILE;
        __half* sBlo = base + 3 * TILE;

        #pragma unroll
        for (int kk = 0; kk < 32; kk += 16) {
            wmma::fragment<wmma::matrix_a, 16, 16, 16, __half, wmma::row_major> aHi[2], aLo[2];
            wmma::fragment<wmma::matrix_b, 16, 16, 16, __half, wmma::col_major> bHi[4], bLo[4];
            #pragma unroll
            for (int ii = 0; ii < 2; ii++) {
                wmma::load_matrix_sync(aHi[ii], &sAhi[(warp_m * 32 + ii * 16) * LDT + kk], LDT);
                wmma::load_matrix_sync(aLo[ii], &sAlo[(warp_m * 32 + ii * 16) * LDT + kk], LDT);
            }
            #pragma unroll
            for (int j = 0; j < 4; j++) {
                wmma::load_matrix_sync(bHi[j], &sBhi[(warp_n * 64 + j * 16) * LDT + kk], LDT);
                if (NT == 4)
                    wmma::load_matrix_sync(bLo[j], &sBlo[(warp_n * 64 + j * 16) * LDT + kk], LDT);
            }
            #pragma unroll
            for (int ii = 0; ii < 2; ii++)
                #pragma unroll
                for (int j = 0; j < 4; j++) {
                    wmma::mma_sync(acc[ii][j], aHi[ii], bHi[j], acc[ii][j]);
                    wmma::mma_sync(acc[ii][j], aLo[ii], bHi[j], acc[ii][j]);
                    if (NT == 4)
                        wmma::mma_sync(acc[ii][j], aHi[ii], bLo[j], acc[ii][j]);
                }
        }
        if (++st == 3) st = 0;
    }
    __syncthreads();

    float* sC = (float*)smem;   // 128 x 132
    #pragma unroll
    for (int ii = 0; ii < 2; ii++)
        #pragma unroll
        for (int j = 0; j < 4; j++)
            wmma::store_matrix_sync(&sC[(warp_m * 32 + ii * 16) * 132 + warp_n * 64 + j * 16],
                                    acc[ii][j], 132, wmma::mem_row_major);
    __syncthreads();

    #pragma unroll
    for (int it = 0; it < 16; it++) {
        int idx = tid + it * 256;            // 0..4095
        int r = idx >> 5, c4 = idx & 31;
        float4 v = *(float4*)&sC[r * 132 + c4 * 4];
        float4 bb = *(const float4*)&bias[n0 + c4 * 4];
        v.x += bb.x; v.y += bb.y; v.z += bb.z; v.w += bb.w;
        size_t off = (size_t)(m0 + r) * N + n0 + c4 * 4;
        if (EPI == 0) {
            *(float4*)&Cf[off] = v;
        } else {
            __half h0 = __float2half_rn(v.x), h1 = __float2half_rn(v.y);
            __half h2 = __float2half_rn(v.z), h3 = __float2half_rn(v.w);
            ((__half2*)(Chi + off))[0] = __halves2half2(h0, h1);
            ((__half2*)(Chi + off))[1] = __halves2half2(h2, h3);
            if (EPI == 2) {
                ((__half2*)(Clo + off))[0] = __halves2half2(__float2half_rn(v.x - __half2float(h0)),
                                                            __float2half_rn(v.y - __half2float(h1)));
                ((__half2*)(Clo + off))[1] = __halves2half2(__float2half_rn(v.z - __half2float(h2)),
                                                            __float2half_rn(v.w - __half2float(h3)));
            }
        }
    }
}

// ---------------------------------------------------------------------------
// Tensor-core scores (lower-tri blocks only): 2-term (Khi+Klo)·Qhi, /32.
// ---------------------------------------------------------------------------
#define LDS 72
__global__ __launch_bounds__(256)
void scores_tc(const __half* __restrict__ Khi, const __half* __restrict__ Klo,
               const __half* __restrict__ Qhi, float* __restrict__ S) {
    if (blockIdx.x > blockIdx.y) return;
    __shared__ __half sKhi[64 * LDS], sKlo[64 * LDS], sQhi[64 * LDS];
    const int bh = blockIdx.z;
    const int b = bh >> 4, h = bh & 15;
    const int kt0 = blockIdx.y * 64, qt0 = blockIdx.x * 64;
    const int tid = threadIdx.x, wid = tid >> 5;
    const int warp_m = wid >> 1, warp_n = wid & 1;

    const size_t baseK = (size_t)(b * TT + kt0) * DD + h * HDIM;
    const size_t baseQ = (size_t)(b * TT + qt0) * DD + h * HDIM;
    #pragma unroll
    for (int u = tid; u < 512; u += 256) {
        int r = u >> 3, cq = u & 7;
        *(uint4*)(&sKhi[r * LDS + cq * 8]) = ((const uint4*)(Khi + baseK + (size_t)r * DD))[cq];
        *(uint4*)(&sKlo[r * LDS + cq * 8]) = ((const uint4*)(Klo + baseK + (size_t)r * DD))[cq];
        *(uint4*)(&sQhi[r * LDS + cq * 8]) = ((const uint4*)(Qhi + baseQ + (size_t)r * DD))[cq];
    }
    __syncthreads();

    wmma::fragment<wmma::accumulator, 16, 16, 16, float> acc[2];
    wmma::fill_fragment(acc[0], 0.0f);
    wmma::fill_fragment(acc[1], 0.0f);

    #pragma unroll
    for (int kk = 0; kk < 64; kk += 16) {
        wmma::fragment<wmma::matrix_a, 16, 16, 16, __half, wmma::row_major> aHi, aLo;
        wmma::fragment<wmma::matrix_b, 16, 16, 16, __half, wmma::col_major> bHi[2];
        wmma::load_matrix_sync(aHi, &sKhi[(warp_m * 16) * LDS + kk], LDS);
        wmma::load_matrix_sync(aLo, &sKlo[(warp_m * 16) * LDS + kk], LDS);
        #pragma unroll
        for (int j = 0; j < 2; j++)
            wmma::load_matrix_sync(bHi[j], &sQhi[(warp_n * 32 + j * 16) * LDS + kk], LDS);
        #pragma unroll
        for (int j = 0; j < 2; j++) {
            wmma::mma_sync(acc[j], aHi, bHi[j], acc[j]);
            wmma::mma_sync(acc[j], aLo, bHi[j], acc[j]);
        }
    }
    #pragma unroll
    for (int j = 0; j < 2; j++) {
        #pragma unroll
        for (int e = 0; e < acc[j].num_elements; e++) acc[j].x[e] *= 0.03125f;
        float* sp = S + (size_t)bh * TT * TT + (size_t)(kt0 + warp_m * 16) * TT
                      + qt0 + warp_n * 32 + j * 16;
        wmma::store_matrix_sync(sp, acc[j], TT, wmma::mem_row_major);
    }
}

// ---------------------------------------------------------------------------
// Fused masked softmax + transposed wout + fp16 weights (hi only).
// Vectorized: float4 loads (one masked boundary chunk), predicate-free
// exp/sum (masked lanes carry -inf -> exp==0), half2 whi writes (full row),
// float4 wout writes. 512 threads = 16 warps, one warp per head.
// ---------------------------------------------------------------------------
#define SMLD 1033
__global__ __launch_bounds__(512)
void fused_sm(const float* __restrict__ S, float* __restrict__ wout,
              __half* __restrict__ whi) {
    extern __shared__ float tile[];   // 16 * SMLD
    const int bkt = blockIdx.x;
    const int b = bkt >> 10, kt = bkt & 1023;
    const int h = threadIdx.x >> 5, lane = threadIdx.x & 31;

    const size_t rowoff = ((size_t)(b * HH + h) * TT + kt) * TT;
    const float4* row4 = (const float4*)(S + rowoff);
    __half2* hrow2 = (__half2*)(whi + rowoff);

    const int ktc = kt >> 2;      // chunk containing kt
    const int ktr = kt & 3;       // valid elems in that chunk - 1
    float v[32];
    float m = NEG_INF;
    #pragma unroll
    for (int i = 0; i < 8; i++) {
        int c = lane + i * 32;    // float4 chunk id 0..255
        float4 f;
        if (c < ktc) {
            f = row4[c];
        } else if (c == ktc) {
            f = row4[c];
            if (ktr < 3) f.w = NEG_INF;
            if (ktr < 2) f.z = NEG_INF;
            if (ktr < 1) f.y = NEG_INF;
        } else {
            f.x = f.y = f.z = f.w = NEG_INF;
        }
        v[4*i] = f.x; v[4*i+1] = f.y; v[4*i+2] = f.z; v[4*i+3] = f.w;
        m = fmaxf(m, fmaxf(fmaxf(f.x, f.y), fmaxf(f.z, f.w)));
    }
    #pragma unroll
    for (int o = 16; o > 0; o >>= 1) m = fmaxf(m, __shfl_xor_sync(0xffffffffu, m, o));

    float s = 0.f;
    #pragma unroll
    for (int i = 0; i < 32; i++) { v[i] = __expf(v[i] - m); s += v[i]; }
    #pragma unroll
    for (int o = 16; o > 0; o >>= 1) s += __shfl_xor_sync(0xffffffffu, s, o);
    const float inv = 1.0f / s;

    float* trow = tile + h * SMLD;
    #pragma unroll
    for (int i = 0; i < 8; i++) {
        int c = lane + i * 32;
        float w0 = v[4*i]   * inv;
        float w1 = v[4*i+1] * inv;
        float w2 = v[4*i+2] * inv;
        float w3 = v[4*i+3] * inv;
        int q = c * 4;
        trow[q]   = w0; trow[q+1] = w1; trow[q+2] = w2; trow[q+3] = w3;
        hrow2[2*c]   = __floats2half2_rn(w0, w1);
        hrow2[2*c+1] = __floats2half2_rn(w2, w3);
    }
    __syncthreads();

    // wout[b,kt,q,h]: float4 over h (4 heads per store), linear in idx4
    float4* wo4 = (float4*)(wout + (size_t)bkt * TT * HH);
    #pragma unroll
    for (int it = 0; it < 8; it++) {
        int idx4 = threadIdx.x + it * 512;   // 0..4095
        int q = idx4 >> 2, hb = (idx4 & 3) * 4;
        float4 o;
        o.x = tile[(hb + 0) * SMLD + q];
        o.y = tile[(hb + 1) * SMLD + q];
        o.z = tile[(hb + 2) * SMLD + q];
        o.w = tile[(hb + 3) * SMLD + q];
        wo4[idx4] = o;
    }
}

// ---------------------------------------------------------------------------
// Tensor-core AV: 1-term Whi·Vhi, split epilogue -> ahi/alo
// ---------------------------------------------------------------------------
__global__ __launch_bounds__(256)
void av_tc(const __half* __restrict__ Whi, const __half* __restrict__ Vhi,
           __half* __restrict__ Ahi, __half* __restrict__ Alo) {
    __shared__ __align__(16) char smraw[2 * 64 * LDS * 2 + 64 * 68 * 4];
    __half* sWhi = (__half*)smraw;
    __half* sVhi = sWhi + 64 * LDS;

    const int bh = blockIdx.y;
    const int b = bh >> 4, h = bh & 15;
    const int m0 = blockIdx.x * 64;
    const int tid = threadIdx.x, wid = tid >> 5;
    const int warp_m = wid >> 1, warp_n = wid & 1;

    const __half* Wh = Whi + (size_t)bh * TT * TT;
    const size_t vbase = (size_t)b * TT * DD + h * HDIM;

    wmma::fragment<wmma::accumulator, 16, 16, 16, float> acc[2];
    wmma::fill_fragment(acc[0], 0.0f);
    wmma::fill_fragment(acc[1], 0.0f);

    const int kend = m0 + 64;
    for (int q0 = 0; q0 < kend; q0 += 64) {
        #pragma unroll
        for (int u = tid; u < 512; u += 256) {
            int r = u >> 3, cq = u & 7;
            size_t offW = (size_t)(m0 + r) * TT + q0;
            *(uint4*)(&sWhi[r * LDS + cq * 8]) = ((const uint4*)(Wh + offW))[cq];
            *(uint4*)(&sVhi[r * LDS + cq * 8]) = ((const uint4*)(Vhi + vbase + (size_t)(q0 + r) * DD))[cq];
        }
        __syncthreads();
        #pragma unroll
        for (int kk = 0; kk < 64; kk += 16) {
            wmma::fragment<wmma::matrix_a, 16, 16, 16, __half, wmma::row_major> aHi;
            wmma::fragment<wmma::matrix_b, 16, 16, 16, __half, wmma::row_major> bHi[2];
            wmma::load_matrix_sync(aHi, &sWhi[(warp_m * 16) * LDS + kk], LDS);
            #pragma unroll
            for (int j = 0; j < 2; j++)
                wmma::load_matrix_sync(bHi[j], &sVhi[kk * LDS + warp_n * 32 + j * 16], LDS);
            #pragma unroll
            for (int j = 0; j < 2; j++)
                wmma::mma_sync(acc[j], aHi, bHi[j], acc[j]);
        }
        __syncthreads();
    }

    float* sC = (float*)(smraw + 2 * 64 * LDS * 2);   // 64 x 68
    #pragma unroll
    for (int j = 0; j < 2; j++)
        wmma::store_matrix_sync(&sC[(warp_m * 16) * 68 + warp_n * 32 + j * 16],
                                acc[j], 68, wmma::mem_row_major);
    __syncthreads();

    #pragma unroll
    for (int it = 0; it < 4; it++) {
        int idx = tid + it * 256;            // 0..1023
        int r = idx >> 4, c4 = idx & 15;
        float4 v = *(float4*)&sC[r * 68 + c4 * 4];
        size_t off = (size_t)(b * TT + m0 + r) * DD + h * HDIM + c4 * 4;
        __half h0 = __float2half_rn(v.x), h1 = __float2half_rn(v.y);
        __half h2 = __float2half_rn(v.z), h3 = __float2half_rn(v.w);
        ((__half2*)(Ahi + off))[0] = __halves2half2(h0, h1);
        ((__half2*)(Ahi + off))[1] = __halves2half2(h2, h3);
        ((__half2*)(Alo + off))[0] = __halves2half2(__float2half_rn(v.x - __half2float(h0)),
                                                    __float2half_rn(v.y - __half2float(h1)));
        ((__half2*)(Alo + off))[1] = __halves2half2(__float2half_rn(v.z - __half2float(h2)),
                                                    __float2half_rn(v.w - __half2float(h3)));
    }
}

// ---------------------------------------------------------------------------
extern "C" void kernel_launch(void* const* d_in, const int* in_sizes, int n_in,
                              void* d_out, int out_size) {
    const float* x  = (const float*)d_in[0];
    const float* Wk = (const float*)d_in[4];
    const float* bk = (const float*)d_in[5];
    const float* Wq = (const float*)d_in[6];
    const float* bq = (const float*)d_in[7];
    const float* Wv = (const float*)d_in[8];
    const float* bv = (const float*)d_in[9];
    const float* Wp = (const float*)d_in[10];
    const float* bp = (const float*)d_in[11];

    float* out  = (float*)d_out;
    float* wout = out + (size_t)BT * DD;

    float* gs;
    __half *xhi, *xlo, *whi, *wplo, *khi, *klo, *qhi, *vhi, *ahi, *alo, *swhi;
    cudaGetSymbolAddress((void**)&gs, g_s);
    cudaGetSymbolAddress((void**)&xhi, g_xhi);
    cudaGetSymbolAddress((void**)&xlo, g_xlo);
    cudaGetSymbolAddress((void**)&whi, g_whi);
    cudaGetSymbolAddress((void**)&wplo, g_wplo);
    cudaGetSymbolAddress((void**)&khi, g_khi);
    cudaGetSymbolAddress((void**)&klo, g_klo);
    cudaGetSymbolAddress((void**)&qhi, g_qhi);
    cudaGetSymbolAddress((void**)&vhi, g_vhi);
    cudaGetSymbolAddress((void**)&ahi, g_ahi);
    cudaGetSymbolAddress((void**)&alo, g_alo);
    cudaGetSymbolAddress((void**)&swhi, g_swhi);

    const size_t WSZ = (size_t)DD * DD;

    const size_t gsm3 = (size_t)3 * 3 * 128 * LDT * sizeof(__half);   // 110592
    const size_t gsm4 = (size_t)3 * 4 * 128 * LDT * sizeof(__half);   // 147456
    cudaFuncSetAttribute(gemm_fp16<3, 1>, cudaFuncAttributeMaxDynamicSharedMemorySize, (int)gsm3);
    cudaFuncSetAttribute(gemm_fp16<3, 2>, cudaFuncAttributeMaxDynamicSharedMemorySize, (int)gsm3);
    cudaFuncSetAttribute(gemm_fp16<4, 0>, cudaFuncAttributeMaxDynamicSharedMemorySize, (int)gsm4);
    const size_t smsz = (size_t)HH * SMLD * sizeof(float);            // 66112
    cudaFuncSetAttribute(fused_sm, cudaFuncAttributeMaxDynamicSharedMemorySize, (int)smsz);

    cvt_all<<<dim3(4096, 5), 256>>>(x, Wk, Wq, Wv, Wp, xhi, xlo, whi, wplo);

    dim3 ggrid(DD / 128, BT / 128);
    gemm_fp16<3, 2><<<ggrid, 256, gsm3>>>(xhi, xlo, whi + 0 * WSZ, nullptr, bk,
                                          nullptr, khi, klo, BT, DD, DD);
    gemm_fp16<3, 1><<<ggrid, 256, gsm3>>>(xhi, xlo, whi + 1 * WSZ, nullptr, bq,
                                          nullptr, qhi, nullptr, BT, DD, DD);
    gemm_fp16<3, 1><<<ggrid, 256, gsm3>>>(xhi, xlo, whi + 2 * WSZ, nullptr, bv,
                                          nullptr, vhi, nullptr, BT, DD, DD);

    dim3 sc_grid(TT / 64, TT / 64, BB * HH);
    scores_tc<<<sc_grid, 256>>>(khi, klo, qhi, gs);

    fused_sm<<<BB * TT, 512, smsz>>>(gs, wout, swhi);

    dim3 av_grid(TT / 64, BB * HH);
    av_tc<<<av_grid, 256>>>(swhi, vhi, ahi, alo);

    dim3 pgrid(DD / 128, BT / 128);
    gemm_fp16<4, 0><<<pgrid, 256, gsm4>>>(ahi, alo, whi + 3 * WSZ, wplo, bp,
                                          out, nullptr, nullptr, BT, DD, DD);
}